// round 16
// baseline (speedup 1.0000x reference)
#include <cuda_runtime.h>
#include <math.h>

// Shapes
// x:  [32, 112, 112, 128] fp32  -> B=32, HW=12544, C=128
// w1: [128, 2048], b1: [2048], w2: [2048, 128], b2: [128]
#define B      32
#define HW     12544
#define C      128
#define R      2048
#define NSPLIT 98
#define NTOTAL (B * NSPLIT)                  // 3136 splits
#define F4_PER_B  (HW * C / 4)               // 401408 float4 per batch
#define F4_PER_BLK (128 * C / 4)             // 4096 float4 per split
#define ECHUNKS 8                            // excite chunks per batch (256 r each)
#define NEBLK  (B * ECHUNKS)                 // 256 excite blocks

// Scratch (device globals: allocation-free; counters self-reset -> replay-safe)
__device__ __align__(16) float g_partial[NTOTAL * C];   // 1.6 MB pool partials
__device__ __align__(16) float g_gp[B * ECHUNKS * C];   // gate partials, 128 KB
__device__ unsigned g_ecnt[B];                          // excite completions / batch
__device__ unsigned g_scnt[B];                          // scale completions / batch

// ---------------------------------------------------------------------------
// Kernel 1: partial pooling sums.  grid (NSPLIT, B), 256 threads.
// EXACT R5 body (proven 33 us @ 80% DRAM) — untouched.
// ---------------------------------------------------------------------------
__global__ __launch_bounds__(256, 8)
void se_pool_kernel(const float* __restrict__ x) {
    const int b = blockIdx.y;
    const int split = blockIdx.x;
    const float4* __restrict__ xb =
        reinterpret_cast<const float4*>(x) + (size_t)b * F4_PER_B + (size_t)split * F4_PER_BLK;
    const int t = threadIdx.x;

    float4 acc = make_float4(0.f, 0.f, 0.f, 0.f);
#pragma unroll
    for (int i = 0; i < 16; i++) {           // 16 * 256 = 4096 float4
        float4 v = xb[t + i * 256];
        acc.x += v.x; acc.y += v.y; acc.z += v.z; acc.w += v.w;
    }

    __shared__ float4 sh[256];
    sh[t] = acc;
    __syncthreads();

    if (t < 32) {
        float4 s = sh[t];
#pragma unroll
        for (int j = 1; j < 8; j++) {
            float4 v = sh[t + j * 32];
            s.x += v.x; s.y += v.y; s.z += v.z; s.w += v.w;
        }
        reinterpret_cast<float4*>(g_partial)[(size_t)(b * NSPLIT + split) * 32 + t] = s;
    }
}

// ---------------------------------------------------------------------------
// Kernel 2: excite + scale in one launch.  grid (NEBLK + NTOTAL), 256 thr.
//   bid <  NEBLK : excite chunk block — reduce batch partials, GEMM1+GELU for
//                  a 256-r chunk, GEMM2 partial -> g_gp, bump g_ecnt[b].
//   bid >= NEBLK : scale block — spin (nanosleep) until its batch's 8 excite
//                  chunks are done, finalize gate, then the R5 streaming body.
// Wave-1 fills in block order, so all 256 excite blocks are resident first
// -> no deadlock.  The 98th scale block per batch resets both counters.
// ---------------------------------------------------------------------------
__global__ __launch_bounds__(256, 6)
void se_excite_scale_kernel(const float* __restrict__ x,
                            const float* __restrict__ w1, const float* __restrict__ b1,
                            const float* __restrict__ w2, const float* __restrict__ b2,
                            float* __restrict__ out) {
    const int t = threadIdx.x;

    if (blockIdx.x < NEBLK) {
        // ------------------ excite chunk path (proven R11 shape) ------------
        const int b = blockIdx.x >> 3;
        const int e = blockIdx.x & 7;        // chunk of 256 r's

        __shared__ float s_mean[C];
        __shared__ float h_sh[256];
        __shared__ float red[256];

        // a) reduce pool partials -> mean s[128]
        if (t < C) {
            const float* p = g_partial + (size_t)b * NSPLIT * C + t;
            float acc = 0.f;
#pragma unroll 14
            for (int k = 0; k < NSPLIT; k++) acc += p[(size_t)k * C];
            s_mean[t] = acc * (1.0f / (float)HW);
        }
        __syncthreads();

        // b) GEMM1 + tanh-approx GELU: one r per thread (coalesced w1 cols)
        {
            const int r = e * 256 + t;
            float acc = b1[r];
#pragma unroll 16
            for (int c = 0; c < C; c++) acc += s_mean[c] * w1[(size_t)c * R + r];
            float u = acc;
            float inner = 0.7978845608028654f * (u + 0.044715f * u * u * u);
            h_sh[t] = 0.5f * u * (1.0f + tanhf(inner));
        }
        __syncthreads();

        // c) GEMM2 partial over this 256-r chunk: c = t%128, half = t/128
        {
            const int c = t & (C - 1);
            const int half = t >> 7;
            const int rbase = e * 256 + half * 128;
            const float* w2s = w2 + (size_t)rbase * C + c;
            float acc = 0.f;
#pragma unroll 16
            for (int rr = 0; rr < 128; rr++)
                acc += h_sh[half * 128 + rr] * w2s[(size_t)rr * C];
            red[t] = acc;
        }
        __syncthreads();
        if (t < C)
            g_gp[((size_t)b * ECHUNKS + e) * C + t] = red[t] + red[t + 128];

        // publish, then signal completion
        __threadfence();
        __syncthreads();
        if (t == 0) atomicAdd(&g_ecnt[b], 1u);
        return;
    }

    // ------------------ scale path (proven R5 body + spin prologue) ---------
    const int rid = (NTOTAL - 1) - (int)(blockIdx.x - NEBLK);  // reversed
    const int b   = rid / NSPLIT;
    const int blk = rid % NSPLIT;

    if (t == 0) {
        while (*(volatile unsigned*)&g_ecnt[b] < ECHUNKS) { __nanosleep(128); }
    }
    __syncthreads();
    __threadfence();                          // acquire g_gp

    // gate for this thread's fixed 4-channel group (L1-bypassing loads)
    const int c4 = (t * 4) & (C - 1);
    float4 g4;
    {
        float4 a = *reinterpret_cast<const float4*>(b2 + c4);
#pragma unroll
        for (int j = 0; j < ECHUNKS; j++) {
            const float* gp = g_gp + ((size_t)b * ECHUNKS + j) * C + c4;
            a.x += __ldcg(&gp[0]);
            a.y += __ldcg(&gp[1]);
            a.z += __ldcg(&gp[2]);
            a.w += __ldcg(&gp[3]);
        }
        g4.x = 1.0f / (1.0f + __expf(-a.x));
        g4.y = 1.0f / (1.0f + __expf(-a.y));
        g4.z = 1.0f / (1.0f + __expf(-a.z));
        g4.w = 1.0f / (1.0f + __expf(-a.w));
    }

    const size_t base = (size_t)b * F4_PER_B + (size_t)blk * F4_PER_BLK;
    const float4* __restrict__ xi = reinterpret_cast<const float4*>(x) + base;
    float4* __restrict__ xo = reinterpret_cast<float4*>(out) + base;

#pragma unroll
    for (int i = 0; i < 16; i++) {
        float4 v = __ldcs(&xi[t + i * 256]);   // dead after use: evict-first
        v.x *= g4.x; v.y *= g4.y; v.z *= g4.z; v.w *= g4.w;
        __stcs(&xo[t + i * 256], v);           // streaming store
    }

    // completion accounting; 98th scale block per batch resets both counters
    if (t == 0) {
        unsigned old = atomicAdd(&g_scnt[b], 1u);
        if (old == NSPLIT - 1) {
            g_ecnt[b] = 0;
            g_scnt[b] = 0;
            __threadfence();
        }
    }
}

extern "C" void kernel_launch(void* const* d_in, const int* in_sizes, int n_in,
                              void* d_out, int out_size) {
    const float* x  = (const float*)d_in[0];
    const float* w1 = (const float*)d_in[1];
    const float* b1 = (const float*)d_in[2];
    const float* w2 = (const float*)d_in[3];
    const float* b2 = (const float*)d_in[4];
    float* out = (float*)d_out;

    se_pool_kernel<<<dim3(NSPLIT, B), 256>>>(x);
    se_excite_scale_kernel<<<NEBLK + NTOTAL, 256>>>(x, w1, b1, w2, b2, out);
}